// round 15
// baseline (speedup 1.0000x reference)
#include <cuda_runtime.h>
#include <cuda_fp16.h>
#include <math.h>
#include <stdint.h>

#define BB   4
#define LL   1024
#define DM   512
#define DI   1024
#define DS   64
#define NH   16
#define CD   1152
#define DIP  2192
#define MM   (BB*LL)

#define NW_IN   (DIP*DM)
#define NW_OUT  (DM*DI)
#define W_IN0   0
#define W_OUT0  (2*NW_IN)
#define W_PROJ  (2*NW_IN + 2*NW_OUT)
#define W_TOT   (W_PROJ + DM*2*DM)

#define NCHK 16
#define TCH  (LL/NCHK)     // 64 timesteps per chunk

__device__ __align__(128) __half g_h   [MM*DM];
__device__ __align__(128) __half g_zx  [2][MM*DIP];
__device__ __align__(128) __half g_conv[2][MM*CD];
__device__ __align__(128) float  g_dt  [2][MM*NH];
__device__ __align__(128) float  g_dec [2][MM*NH];
__device__ __align__(128) float  g_y   [2][MM*DI];
__device__ __align__(128) __half g_yh  [2][MM*DI];
__device__ __align__(128) __half g_cat [MM*2*DM];
__device__ __align__(128) __half g_wh  [W_TOT];
__device__ __align__(128) float  g_hloc[2*BB*NH*NCHK*64*64];  // chunk-final states
__device__ __align__(128) float  g_hini[2*BB*NH*NCHK*64*64];  // chunk-initial states
__device__ __align__(128) float  g_pch [2*BB*NH*NCHK];        // per-chunk decay product

// ---------------- helpers ----------------
__device__ __forceinline__ uint32_t cvta_s(const void* p){
    uint32_t a;
    asm("{ .reg .u64 t; cvta.to.shared.u64 t, %1; cvt.u32.u64 %0, t; }":"=r"(a):"l"(p));
    return a;
}
__device__ __forceinline__ void cp16(uint32_t dst, const void* src, int sz){
    asm volatile("{ .reg .u64 g; cvta.to.global.u64 g, %1;\n\t"
                 "cp.async.cg.shared.global [%0], [g], 16, %2; }"
                 :: "r"(dst), "l"(src), "r"(sz) : "memory");
}
__device__ __forceinline__ uint64_t pk2(float a, float b){
    uint64_t r; asm("mov.b64 %0, {%1,%2};" : "=l"(r) : "f"(a), "f"(b)); return r;
}
__device__ __forceinline__ uint64_t ffma2(uint64_t a, uint64_t b, uint64_t c){
    uint64_t d; asm("fma.rn.f32x2 %0, %1, %2, %3;" : "=l"(d) : "l"(a), "l"(b), "l"(c)); return d;
}
__device__ __forceinline__ uint64_t mul2(uint64_t a, uint64_t b){
    uint64_t d; asm("mul.rn.f32x2 %0, %1, %2;" : "=l"(d) : "l"(a), "l"(b)); return d;
}
__device__ __forceinline__ uint64_t add2(uint64_t a, uint64_t b){
    uint64_t d; asm("add.rn.f32x2 %0, %1, %2;" : "=l"(d) : "l"(a), "l"(b)); return d;
}

__device__ __forceinline__ float block_reduce_sum_256(float v, float* red) {
    int tid = threadIdx.x;
    #pragma unroll
    for (int o = 16; o; o >>= 1) v += __shfl_xor_sync(0xffffffffu, v, o);
    if ((tid & 31) == 0) red[tid >> 5] = v;
    __syncthreads();
    float t = (tid < 8) ? red[tid] : 0.f;
    if (tid < 32) {
        #pragma unroll
        for (int o = 4; o; o >>= 1) t += __shfl_xor_sync(0xffffffffu, t, o);
        if (tid == 0) red[0] = t;
    }
    __syncthreads();
    return red[0];
}

// ---- K0: fused weight-convert + input rmsnorm ----------
#define PREP_BLOCKS ((W_TOT + 255) / 256)
__global__ void k_prep_norm(const float* __restrict__ x, const float* __restrict__ nw,
                            const float* __restrict__ iw0, const float* __restrict__ iw1,
                            const float* __restrict__ ow0, const float* __restrict__ ow1,
                            const float* __restrict__ pw)
{
    if (blockIdx.x < PREP_BLOCKS) {
        long long i = (long long)blockIdx.x * 256 + threadIdx.x;
        if (i >= W_TOT) return;
        float v;
        if      (i < NW_IN)              v = iw0[i];
        else if (i < 2*NW_IN)            v = iw1[i - NW_IN];
        else if (i < 2*NW_IN + NW_OUT)   v = ow0[i - 2*NW_IN];
        else if (i < W_PROJ)             v = ow1[i - 2*NW_IN - NW_OUT];
        else                             v = pw [i - W_PROJ];
        g_wh[i] = __float2half_rn(v);
    } else {
        int row = blockIdx.x - PREP_BLOCKS, tid = threadIdx.x;
        const float* xr = x + (size_t)row * DM;
        float v0 = xr[tid], v1 = xr[tid + 256];
        __shared__ float red[8];
        float ss = block_reduce_sum_256(v0 * v0 + v1 * v1, red);
        float scale = rsqrtf(ss / (float)DM + 1e-5f);
        g_h[(size_t)row * DM + tid]       = __float2half_rn(v0 * scale * nw[tid]);
        g_h[(size_t)row * DM + tid + 256] = __float2half_rn(v1 * scale * nw[tid + 256]);
    }
}

// ---------------- K2: fp16 mma.sync NT GEMM (R8 mainloop, best measured) ----
#define ST     3
#define BK     64
#define GPADH  72
#define STAGE_H (128*GPADH)
#define GEMM_SMEM (ST*2*STAGE_H*2)           // 110592 bytes

#define LDSM4(r0,r1,r2,r3,addr) \
    asm volatile("ldmatrix.sync.aligned.m8n8.x4.shared.b16 {%0,%1,%2,%3}, [%4];" \
        : "=r"(r0), "=r"(r1), "=r"(r2), "=r"(r3) : "r"(addr))

__global__ void __launch_bounds__(256, 2) k_gemm(
    const __half* __restrict__ A0, long long sA,
    const __half* __restrict__ B0, long long sB,
    void* C0, long long sC,
    const float* __restrict__ R,
    int N, int K, int ldc, int c_half)
{
    extern __shared__ __half smh[];
    const __half* A  = A0 + (size_t)blockIdx.z * sA;
    const __half* Bw = B0 + (size_t)blockIdx.z * sB;

    uint32_t sbase = cvta_s(smh);
    int tid = threadIdx.x, warp = tid >> 5, lane = tid & 31;
    int grp = lane >> 2, tig = lane & 3;
    int m0 = blockIdx.y * 128, n0 = blockIdx.x * 128;
    int mb = (warp & 1) * 64, nb2 = (warp >> 1) * 32;

    float c[4][4][4];
    #pragma unroll
    for (int mi = 0; mi < 4; mi++)
        #pragma unroll
        for (int ni = 0; ni < 4; ni++)
            #pragma unroll
            for (int q = 0; q < 4; q++) c[mi][ni][q] = 0.f;

    const int nk = K / BK;

    uint32_t aoff[4], boff[2];
    {
        int l15 = lane & 15;
        int khalf = (lane >> 4) * 8;
        #pragma unroll
        for (int mi = 0; mi < 4; mi++)
            aoff[mi] = (uint32_t)((mb + mi * 16 + l15) * GPADH + khalf) * 2;
        int brow = (lane & 7) + ((lane >> 4) << 3);
        int bkh  = (lane & 8) ? 8 : 0;
        #pragma unroll
        for (int q = 0; q < 2; q++)
            boff[q] = (uint32_t)((nb2 + q * 16 + brow) * GPADH + bkh) * 2;
    }

    auto prefetch = [&](int kt){
        int st = kt % ST;
        uint32_t ab = sbase + (uint32_t)(st * 2 * STAGE_H) * 2;
        uint32_t bb = ab + STAGE_H * 2;
        int kc = kt * BK;
        #pragma unroll
        for (int i = 0; i < 4; i++) {
            int id = tid + i * 256, r = id >> 3, c8 = (id & 7) * 8;
            uint32_t off = (uint32_t)(r * GPADH + c8) * 2;
            cp16(ab + off, &A[(size_t)(m0 + r) * K + kc + c8], 16);
            int nr = n0 + r;
            cp16(bb + off, &Bw[(size_t)(nr < N ? nr : 0) * K + kc + c8],
                 nr < N ? 16 : 0);
        }
        asm volatile("cp.async.commit_group;" ::: "memory");
    };

    prefetch(0); prefetch(1); prefetch(2);

    for (int kt = 0; kt < nk; kt++) {
        int allow = nk - 1 - kt; if (allow > ST - 1) allow = ST - 1;
        switch (allow) {
            case 2: asm volatile("cp.async.wait_group 2;" ::: "memory"); break;
            case 1: asm volatile("cp.async.wait_group 1;" ::: "memory"); break;
            default: asm volatile("cp.async.wait_group 0;" ::: "memory"); break;
        }
        __syncthreads();

        int st = kt % ST;
        uint32_t Ast = sbase + (uint32_t)(st * 2 * STAGE_H) * 2;
        uint32_t Bst = Ast + STAGE_H * 2;

        #pragma unroll
        for (int s = 0; s < 4; s++) {
            uint32_t kb = (uint32_t)(s * 16) * 2;
            uint32_t a[4][4], b[4][2];
            #pragma unroll
            for (int mi = 0; mi < 4; mi++)
                LDSM4(a[mi][0], a[mi][1], a[mi][2], a[mi][3], Ast + aoff[mi] + kb);
            #pragma unroll
            for (int q = 0; q < 2; q++)
                LDSM4(b[2*q][0], b[2*q][1], b[2*q+1][0], b[2*q+1][1],
                      Bst + boff[q] + kb);
            #pragma unroll
            for (int mi = 0; mi < 4; mi++)
                #pragma unroll
                for (int ni = 0; ni < 4; ni++) {
                    asm volatile(
                        "mma.sync.aligned.m16n8k16.row.col.f32.f16.f16.f32 "
                        "{%0,%1,%2,%3}, {%4,%5,%6,%7}, {%8,%9}, {%0,%1,%2,%3};"
                        : "+f"(c[mi][ni][0]), "+f"(c[mi][ni][1]),
                          "+f"(c[mi][ni][2]), "+f"(c[mi][ni][3])
                        : "r"(a[mi][0]), "r"(a[mi][1]), "r"(a[mi][2]), "r"(a[mi][3]),
                          "r"(b[ni][0]), "r"(b[ni][1]));
                }
        }
        __syncthreads();
        if (kt + ST < nk) prefetch(kt + ST);
    }

    if (c_half) {
        __half* C = (__half*)C0 + (size_t)blockIdx.z * sC;
        #pragma unroll
        for (int mi = 0; mi < 4; mi++) {
            int row = m0 + mb + mi * 16 + grp;
            #pragma unroll
            for (int ni = 0; ni < 4; ni++) {
                int col = n0 + nb2 + ni * 8 + tig * 2;
                if (col < N) {
                    __half2 h0 = __floats2half2_rn(c[mi][ni][0], c[mi][ni][1]);
                    __half2 h1 = __floats2half2_rn(c[mi][ni][2], c[mi][ni][3]);
                    *(__half2*)&C[(size_t)row * ldc + col]       = h0;
                    *(__half2*)&C[(size_t)(row + 8) * ldc + col] = h1;
                }
            }
        }
    } else {
        float* C = (float*)C0 + (size_t)blockIdx.z * sC;
        #pragma unroll
        for (int mi = 0; mi < 4; mi++) {
            int row = m0 + mb + mi * 16 + grp;
            #pragma unroll
            for (int ni = 0; ni < 4; ni++) {
                int col = n0 + nb2 + ni * 8 + tig * 2;
                if (col < N) {
                    float v0 = c[mi][ni][0], v1 = c[mi][ni][1];
                    float v2 = c[mi][ni][2], v3 = c[mi][ni][3];
                    if (R) {
                        float2 r0 = *(const float2*)&R[(size_t)row * ldc + col];
                        float2 r1 = *(const float2*)&R[(size_t)(row + 8) * ldc + col];
                        v0 += r0.x; v1 += r0.y; v2 += r1.x; v3 += r1.y;
                    }
                    *(float2*)&C[(size_t)row * ldc + col]       = make_float2(v0, v1);
                    *(float2*)&C[(size_t)(row + 8) * ldc + col] = make_float2(v2, v3);
                }
            }
        }
    }
}

// ---------------- K3: conv1d + silu, 8 channels/thread + dt ----------------
__global__ void k_conv3(const float* __restrict__ fw, const float* __restrict__ fb,
                        const float* __restrict__ bw2, const float* __restrict__ bb,
                        const float* __restrict__ fdtb, const float* __restrict__ fA,
                        const float* __restrict__ bdtb, const float* __restrict__ bA)
{
    int token = blockIdx.x, dir = blockIdx.y;
    int b = token >> 10, s = token & 1023;
    const float* w  = dir ? bw2 : fw;
    const float* cb = dir ? bb : fb;
    const __half* zx = g_zx[dir];
    int c = threadIdx.x * 8;

    float acc[8];
    #pragma unroll
    for (int j = 0; j < 8; j++) acc[j] = cb[c + j];
    float wt[8][4];
    #pragma unroll
    for (int j = 0; j < 8; j++) {
        float4 wv = *(const float4*)&w[(c + j) * 4];
        wt[j][0] = wv.x; wt[j][1] = wv.y; wt[j][2] = wv.z; wt[j][3] = wv.w;
    }

    #pragma unroll
    for (int k = 0; k < 4; k++) {
        int sp = dir ? (s + 3 - k) : (s - 3 + k);
        if (sp >= 0 && sp < LL) {
            uint4 u = *(const uint4*)&zx[(size_t)(b * LL + sp) * DIP + DI + c];
            float2 f0 = __half22float2(*(__half2*)&u.x);
            float2 f1 = __half22float2(*(__half2*)&u.y);
            float2 f2 = __half22float2(*(__half2*)&u.z);
            float2 f3 = __half22float2(*(__half2*)&u.w);
            acc[0] = fmaf(f0.x, wt[0][k], acc[0]);
            acc[1] = fmaf(f0.y, wt[1][k], acc[1]);
            acc[2] = fmaf(f1.x, wt[2][k], acc[2]);
            acc[3] = fmaf(f1.y, wt[3][k], acc[3]);
            acc[4] = fmaf(f2.x, wt[4][k], acc[4]);
            acc[5] = fmaf(f2.y, wt[5][k], acc[5]);
            acc[6] = fmaf(f3.x, wt[6][k], acc[6]);
            acc[7] = fmaf(f3.y, wt[7][k], acc[7]);
        }
    }
    __half2 ho[4];
    #pragma unroll
    for (int j = 0; j < 4; j++) {
        float a0 = acc[2*j],   s0 = a0 / (1.f + __expf(-a0));
        float a1 = acc[2*j+1], s1 = a1 / (1.f + __expf(-a1));
        ho[j] = __floats2half2_rn(s0, s1);
    }
    uint4 uo;
    uo.x = *(uint32_t*)&ho[0]; uo.y = *(uint32_t*)&ho[1];
    uo.z = *(uint32_t*)&ho[2]; uo.w = *(uint32_t*)&ho[3];
    *(uint4*)&g_conv[dir][(size_t)token * CD + c] = uo;

    if (threadIdx.x < NH) {
        int h = threadIdx.x;
        float v = __half2float(zx[(size_t)token * DIP + DI + CD + h]) + (dir ? bdtb : fdtb)[h];
        float dt = (v > 20.f) ? v : log1pf(expf(v));
        g_dt[dir][token * NH + h]  = dt;
        g_dec[dir][token * NH + h] = expf(-dt * expf((dir ? bA : fA)[h]));
    }
}

// ---- K4a: PASS 1 — chunk-local states only (no y, no C, no shfl) ------------
#define TC 8
__global__ void __launch_bounds__(256, 4) k_scan_state()
{
    int blk = blockIdx.x;
    int ch  = blk % NCHK;
    int dbh = blk / NCHK;
    int dir = dbh >> 6, b = (dbh >> 4) & 3, h = dbh & 15;
    const __half* conv = g_conv[dir];
    const float* dts  = g_dt[dir];
    const float* decs = g_dec[dir];

    int tid = threadIdx.x;
    int p  = tid >> 2;
    int nb = (tid & 3) * 16;

    int c = -1;
    if (tid < 64)       c = h * 64 + tid;        // x row
    else if (tid < 128) c = DI + (tid - 64);     // B row

    __align__(16) uint64_t st2[8];
    #pragma unroll
    for (int j = 0; j < 8; j++) st2[j] = 0ull;
    float Pcum = 1.f;

    __shared__ __align__(16) float sm[TC][132];  // x 0..63 | B 64..127 | dec@128 | dt@129
    float v[TC];
    const int t0 = ch * TCH;

    auto load_chunk = [&](int g){
        #pragma unroll
        for (int tt = 0; tt < TC; tt++) {
            int t = t0 + g * TC + tt;
            int s = dir ? (LL - 1 - t) : t;
            int token = b * LL + s;
            if (tid < 128)        v[tt] = __half2float(conv[(size_t)token * CD + c]);
            else if (tid == 128)  v[tt] = decs[token * NH + h];
            else if (tid == 129)  v[tt] = dts[token * NH + h];
        }
    };

    load_chunk(0);
    const int NG = TCH / TC;
    for (int g = 0; g < NG; g++) {
        __syncthreads();
        if (tid < 130) {
            #pragma unroll
            for (int tt = 0; tt < TC; tt++) sm[tt][tid] = v[tt];
        }
        __syncthreads();
        if (g + 1 < NG) load_chunk(g + 1);

        #pragma unroll
        for (int tt = 0; tt < TC; tt++) {
            float dec = sm[tt][128], dtv = sm[tt][129], xv = sm[tt][p];
            uint64_t dec2 = pk2(dec, dec);
            uint64_t dtx2 = pk2(dtv * xv, dtv * xv);
            #pragma unroll
            for (int q = 0; q < 4; q++) {
                ulonglong2 bq = *(const ulonglong2*)&sm[tt][64 + nb + q * 4];
                st2[2*q]   = ffma2(st2[2*q],   dec2, mul2(dtx2, bq.x));
                st2[2*q+1] = ffma2(st2[2*q+1], dec2, mul2(dtx2, bq.y));
            }
            Pcum *= dec;
        }
    }

    float* hl = g_hloc + ((size_t)(dbh * NCHK + ch)) * 4096 + (size_t)tid * 16;
    const float4* s4 = (const float4*)st2;
    #pragma unroll
    for (int q = 0; q < 4; q++) *(float4*)&hl[q * 4] = s4[q];
    if (tid == 0) g_pch[dbh * NCHK + ch] = Pcum;
}

// ---- K4b: sequential combine of chunk states -> h_init per chunk ----------
__global__ void __launch_bounds__(256) k_combine()
{
    int dbh = blockIdx.x;
    int tid = threadIdx.x;

    float4 val[4];
    #pragma unroll
    for (int q = 0; q < 4; q++) val[q] = make_float4(0.f, 0.f, 0.f, 0.f);

    for (int j = 0; j < NCHK; j++) {
        float Pc = g_pch[dbh * NCHK + j];
        const float4* hl = (const float4*)(g_hloc +
            ((size_t)(dbh * NCHK + j)) * 4096 + (size_t)tid * 16);
        float4 hv[4];
        #pragma unroll
        for (int q = 0; q < 4; q++) hv[q] = hl[q];
        #pragma unroll
        for (int q = 0; q < 4; q++) {
            val[q].x = fmaf(Pc, val[q].x, hv[q].x);
            val[q].y = fmaf(Pc, val[q].y, hv[q].y);
            val[q].z = fmaf(Pc, val[q].z, hv[q].z);
            val[q].w = fmaf(Pc, val[q].w, hv[q].w);
        }
        if (j + 1 < NCHK) {
            float4* hi = (float4*)(g_hini +
                ((size_t)(dbh * NCHK + j + 1)) * 4096 + (size_t)tid * 16);
            #pragma unroll
            for (int q = 0; q < 4; q++) hi[q] = val[q];
        }
    }
}

// ---- K4c: PASS 2 — full scan seeded with h_init; exact y in one write -------
__global__ void __launch_bounds__(256, 4) k_scan_full(const float* __restrict__ fD,
                                                      const float* __restrict__ bD)
{
    int blk = blockIdx.x;
    int ch  = blk % NCHK;
    int dbh = blk / NCHK;
    int dir = dbh >> 6, b = (dbh >> 4) & 3, h = dbh & 15;
    const __half* conv = g_conv[dir];
    const float* dts  = g_dt[dir];
    const float* decs = g_dec[dir];
    float* y = g_y[dir];
    float Dh = (dir ? bD : fD)[h];

    int tid = threadIdx.x;
    int p  = tid >> 2;
    int nb = (tid & 3) * 16;

    int c = -1;
    if (tid < 64)       c = h * 64 + tid;
    else if (tid < 128) c = DI + (tid - 64);
    else if (tid < 192) c = DI + 64 + (tid - 128);

    __align__(16) uint64_t st2[8];
    if (ch > 0) {
        const float4* hi = (const float4*)(g_hini +
            ((size_t)(dbh * NCHK + ch)) * 4096 + (size_t)tid * 16);
        float4* s4 = (float4*)st2;
        #pragma unroll
        for (int q = 0; q < 4; q++) s4[q] = hi[q];
    } else {
        #pragma unroll
        for (int j = 0; j < 8; j++) st2[j] = 0ull;
    }

    __shared__ __align__(16) float sm[TC][200];
    float v[TC];
    const int t0 = ch * TCH;

    auto load_chunk = [&](int g){
        #pragma unroll
        for (int tt = 0; tt < TC; tt++) {
            int t = t0 + g * TC + tt;
            int s = dir ? (LL - 1 - t) : t;
            int token = b * LL + s;
            if (tid < 192)        v[tt] = __half2float(conv[(size_t)token * CD + c]);
            else if (tid == 192)  v[tt] = decs[token * NH + h];
            else if (tid == 193)  v[tt] = dts[token * NH + h];
        }
    };

    load_chunk(0);
    const int NG = TCH / TC;
    for (int g = 0; g < NG; g++) {
        __syncthreads();
        if (tid < 194) {
            #pragma unroll
            for (int tt = 0; tt < TC; tt++) sm[tt][tid] = v[tt];
        }
        __syncthreads();
        if (g + 1 < NG) load_chunk(g + 1);

        #pragma unroll
        for (int tt = 0; tt < TC; tt++) {
            int t = t0 + g * TC + tt;
            int s = dir ? (LL - 1 - t) : t;
            int token = b * LL + s;
            float dec = sm[tt][192], dtv = sm[tt][193], xv = sm[tt][p];
            uint64_t dec2 = pk2(dec, dec);
            uint64_t dtx2 = pk2(dtv * xv, dtv * xv);
            uint64_t ac[4];
            #pragma unroll
            for (int q = 0; q < 4; q++) {
                ulonglong2 bq = *(const ulonglong2*)&sm[tt][64 + nb + q * 4];
                ulonglong2 cq = *(const ulonglong2*)&sm[tt][128 + nb + q * 4];
                st2[2*q]   = ffma2(st2[2*q],   dec2, mul2(dtx2, bq.x));
                st2[2*q+1] = ffma2(st2[2*q+1], dec2, mul2(dtx2, bq.y));
                ac[q] = mul2(st2[2*q], cq.x);
                ac[q] = ffma2(st2[2*q+1], cq.y, ac[q]);
            }
            uint64_t acc2 = add2(add2(ac[0], ac[1]), add2(ac[2], ac[3]));
            float acc = __uint_as_float((uint32_t)acc2)
                      + __uint_as_float((uint32_t)(acc2 >> 32));
            acc += __shfl_xor_sync(0xffffffffu, acc, 1);
            acc += __shfl_xor_sync(0xffffffffu, acc, 2);
            if ((tid & 3) == 0)
                y[(size_t)token * DI + h * 64 + p] = acc + Dh * xv;
        }
    }
}

// ---------------- K5: gate (y*silu(z)) + rmsnorm -> fp16 ----------
__global__ void k_gatenorm(const float* __restrict__ f_gw, const float* __restrict__ b_gw)
{
    int row = blockIdx.x, dir = blockIdx.y;
    const float* gw = dir ? b_gw : f_gw;
    const __half* z = g_zx[dir] + (size_t)row * DIP;
    const float* y = g_y[dir] + (size_t)row * DI;
    __half* yo = g_yh[dir] + (size_t)row * DI;
    int tid = threadIdx.x;

    float g[4];
    float ss = 0.f;
    #pragma unroll
    for (int i = 0; i < 4; i++) {
        int cidx = tid + i * 256;
        float zv = __half2float(z[cidx]);
        float gv = y[cidx] * (zv / (1.f + __expf(-zv)));
        g[i] = gv;
        ss += gv * gv;
    }
    __shared__ float red[8];
    float tot = block_reduce_sum_256(ss, red);
    float scale = rsqrtf(tot / (float)DI + 1e-5f);
    #pragma unroll
    for (int i = 0; i < 4; i++) {
        int cidx = tid + i * 256;
        yo[cidx] = __float2half_rn(g[i] * scale * gw[cidx]);
    }
}

// ---------------- launcher ----------------
extern "C" void kernel_launch(void* const* d_in, const int* in_sizes, int n_in,
                              void* d_out, int out_size)
{
    (void)in_sizes; (void)n_in; (void)out_size;
    const float* x       = (const float*)d_in[0];
    const float* norm_w  = (const float*)d_in[1];
    const float* in_w[2]   = {(const float*)d_in[2],  (const float*)d_in[10]};
    const float* conv_w[2] = {(const float*)d_in[3],  (const float*)d_in[11]};
    const float* conv_b[2] = {(const float*)d_in[4],  (const float*)d_in[12]};
    const float* dt_b[2]   = {(const float*)d_in[5],  (const float*)d_in[13]};
    const float* A_log[2]  = {(const float*)d_in[6],  (const float*)d_in[14]};
    const float* Dp[2]     = {(const float*)d_in[7],  (const float*)d_in[15]};
    const float* gnorm[2]  = {(const float*)d_in[8],  (const float*)d_in[16]};
    const float* out_w[2]  = {(const float*)d_in[9],  (const float*)d_in[17]};
    const float* proj_w    = (const float*)d_in[18];
    float* out = (float*)d_out;

    __half *p_h, *p_zx, *p_yh, *p_cat, *p_w;
    cudaGetSymbolAddress((void**)&p_h,   g_h);
    cudaGetSymbolAddress((void**)&p_zx,  g_zx);
    cudaGetSymbolAddress((void**)&p_yh,  g_yh);
    cudaGetSymbolAddress((void**)&p_cat, g_cat);
    cudaGetSymbolAddress((void**)&p_w,   g_wh);

    cudaFuncSetAttribute(k_gemm,
                         cudaFuncAttributeMaxDynamicSharedMemorySize, GEMM_SMEM);

    // 0. fused weight prep + input rmsnorm
    k_prep_norm<<<PREP_BLOCKS + MM, 256>>>(x, norm_w, in_w[0], in_w[1],
                                           out_w[0], out_w[1], proj_w);

    // 1. in_proj both dirs
    {
        dim3 grid((DIP + 127) / 128, MM / 128, 2);
        k_gemm<<<grid, 256, GEMM_SMEM>>>(p_h, 0LL,
                                         p_w + W_IN0, (long long)NW_IN,
                                         p_zx, (long long)MM * DIP,
                                         nullptr, DIP, DM, DIP, 1);
    }

    // 2. conv + silu + dt
    {
        dim3 cgrid(MM, 2);
        k_conv3<<<cgrid, CD / 8>>>(conv_w[0], conv_b[0], conv_w[1], conv_b[1],
                                   dt_b[0], A_log[0], dt_b[1], A_log[1]);
    }

    // 3. pass 1: chunk-local states (launch 3 -> profiled)
    k_scan_state<<<128 * NCHK, 256>>>();

    // 4. combine -> h_init per chunk
    k_combine<<<128, 256>>>();

    // 5. pass 2: seeded full scan, exact y
    k_scan_full<<<128 * NCHK, 256>>>(Dp[0], Dp[1]);

    // 6. gate + rmsnorm
    {
        dim3 grid(MM, 2);
        k_gatenorm<<<grid, 256>>>(gnorm[0], gnorm[1]);
    }

    // 7. out_proj both dirs
    {
        dim3 grid(DM / 128, MM / 128, 2);
        k_gemm<<<grid, 256, GEMM_SMEM>>>(p_yh, (long long)MM * DI,
                                         p_w + W_OUT0, (long long)NW_OUT,
                                         p_cat, (long long)DM,
                                         nullptr, DM, DI, 2 * DM, 1);
    }

    // 8. final: out = x + cat @ proj_w^T
    {
        dim3 grid(DM / 128, MM / 128, 1);
        k_gemm<<<grid, 256, GEMM_SMEM>>>(p_cat, 0LL,
                                         p_w + W_PROJ, 0LL,
                                         out, 0LL,
                                         x, DM, 2 * DM, DM, 0);
    }
}

// round 16
// speedup vs baseline: 1.2993x; 1.2993x over previous
#include <cuda_runtime.h>
#include <cuda_fp16.h>
#include <math.h>
#include <stdint.h>

#define BB   4
#define LL   1024
#define DM   512
#define DI   1024
#define DS   64
#define NH   16
#define CD   1152
#define DIP  2192
#define MM   (BB*LL)

#define NW_IN   (DIP*DM)
#define NW_OUT  (DM*DI)
#define W_IN0   0
#define W_OUT0  (2*NW_IN)
#define W_PROJ  (2*NW_IN + 2*NW_OUT)
#define W_TOT   (W_PROJ + DM*2*DM)

__device__ __align__(128) __half g_h   [MM*DM];
__device__ __align__(128) __half g_zx  [2][MM*DIP];
__device__ __align__(128) __half g_conv[2][MM*CD];
__device__ __align__(128) float  g_dt  [2][MM*NH];
__device__ __align__(128) float  g_dec [2][MM*NH];
__device__ __align__(128) float  g_y   [2][MM*DI];
__device__ __align__(128) __half g_yh  [2][MM*DI];
__device__ __align__(128) __half g_cat [MM*2*DM];
__device__ __align__(128) __half g_wh  [W_TOT];

// ---------------- helpers ----------------
__device__ __forceinline__ uint32_t cvta_s(const void* p){
    uint32_t a;
    asm("{ .reg .u64 t; cvta.to.shared.u64 t, %1; cvt.u32.u64 %0, t; }":"=r"(a):"l"(p));
    return a;
}
__device__ __forceinline__ void cp16(uint32_t dst, const void* src, int sz){
    asm volatile("{ .reg .u64 g; cvta.to.global.u64 g, %1;\n\t"
                 "cp.async.cg.shared.global [%0], [g], 16, %2; }"
                 :: "r"(dst), "l"(src), "r"(sz) : "memory");
}
__device__ __forceinline__ uint64_t pk2(float a, float b){
    uint64_t r; asm("mov.b64 %0, {%1,%2};" : "=l"(r) : "f"(a), "f"(b)); return r;
}
__device__ __forceinline__ uint64_t ffma2(uint64_t a, uint64_t b, uint64_t c){
    uint64_t d; asm("fma.rn.f32x2 %0, %1, %2, %3;" : "=l"(d) : "l"(a), "l"(b), "l"(c)); return d;
}
__device__ __forceinline__ uint64_t mul2(uint64_t a, uint64_t b){
    uint64_t d; asm("mul.rn.f32x2 %0, %1, %2;" : "=l"(d) : "l"(a), "l"(b)); return d;
}

__device__ __forceinline__ float block_reduce_sum_256(float v, float* red) {
    int tid = threadIdx.x;
    #pragma unroll
    for (int o = 16; o; o >>= 1) v += __shfl_xor_sync(0xffffffffu, v, o);
    if ((tid & 31) == 0) red[tid >> 5] = v;
    __syncthreads();
    float t = (tid < 8) ? red[tid] : 0.f;
    if (tid < 32) {
        #pragma unroll
        for (int o = 4; o; o >>= 1) t += __shfl_xor_sync(0xffffffffu, t, o);
        if (tid == 0) red[0] = t;
    }
    __syncthreads();
    return red[0];
}

// ---- K0: fused weight-convert + input rmsnorm ----------
#define PREP_BLOCKS ((W_TOT + 255) / 256)
__global__ void k_prep_norm(const float* __restrict__ x, const float* __restrict__ nw,
                            const float* __restrict__ iw0, const float* __restrict__ iw1,
                            const float* __restrict__ ow0, const float* __restrict__ ow1,
                            const float* __restrict__ pw)
{
    if (blockIdx.x < PREP_BLOCKS) {
        long long i = (long long)blockIdx.x * 256 + threadIdx.x;
        if (i >= W_TOT) return;
        float v;
        if      (i < NW_IN)              v = iw0[i];
        else if (i < 2*NW_IN)            v = iw1[i - NW_IN];
        else if (i < 2*NW_IN + NW_OUT)   v = ow0[i - 2*NW_IN];
        else if (i < W_PROJ)             v = ow1[i - 2*NW_IN - NW_OUT];
        else                             v = pw [i - W_PROJ];
        g_wh[i] = __float2half_rn(v);
    } else {
        int row = blockIdx.x - PREP_BLOCKS, tid = threadIdx.x;
        const float* xr = x + (size_t)row * DM;
        float v0 = xr[tid], v1 = xr[tid + 256];
        __shared__ float red[8];
        float ss = block_reduce_sum_256(v0 * v0 + v1 * v1, red);
        float scale = rsqrtf(ss / (float)DM + 1e-5f);
        g_h[(size_t)row * DM + tid]       = __float2half_rn(v0 * scale * nw[tid]);
        g_h[(size_t)row * DM + tid + 256] = __float2half_rn(v1 * scale * nw[tid + 256]);
    }
}

// ---------------- K2: fp16 mma.sync NT GEMM (R8 mainloop, best measured) ----
#define ST     3
#define BK     64
#define GPADH  72
#define STAGE_H (128*GPADH)
#define GEMM_SMEM (ST*2*STAGE_H*2)           // 110592 bytes

#define LDSM4(r0,r1,r2,r3,addr) \
    asm volatile("ldmatrix.sync.aligned.m8n8.x4.shared.b16 {%0,%1,%2,%3}, [%4];" \
        : "=r"(r0), "=r"(r1), "=r"(r2), "=r"(r3) : "r"(addr))

__global__ void __launch_bounds__(256, 2) k_gemm(
    const __half* __restrict__ A0, long long sA,
    const __half* __restrict__ B0, long long sB,
    void* C0, long long sC,
    const float* __restrict__ R,
    int N, int K, int ldc, int c_half)
{
    extern __shared__ __half smh[];
    const __half* A  = A0 + (size_t)blockIdx.z * sA;
    const __half* Bw = B0 + (size_t)blockIdx.z * sB;

    uint32_t sbase = cvta_s(smh);
    int tid = threadIdx.x, warp = tid >> 5, lane = tid & 31;
    int grp = lane >> 2, tig = lane & 3;
    int m0 = blockIdx.y * 128, n0 = blockIdx.x * 128;
    int mb = (warp & 1) * 64, nb2 = (warp >> 1) * 32;

    float c[4][4][4];
    #pragma unroll
    for (int mi = 0; mi < 4; mi++)
        #pragma unroll
        for (int ni = 0; ni < 4; ni++)
            #pragma unroll
            for (int q = 0; q < 4; q++) c[mi][ni][q] = 0.f;

    const int nk = K / BK;

    uint32_t aoff[4], boff[2];
    {
        int l15 = lane & 15;
        int khalf = (lane >> 4) * 8;
        #pragma unroll
        for (int mi = 0; mi < 4; mi++)
            aoff[mi] = (uint32_t)((mb + mi * 16 + l15) * GPADH + khalf) * 2;
        int brow = (lane & 7) + ((lane >> 4) << 3);
        int bkh  = (lane & 8) ? 8 : 0;
        #pragma unroll
        for (int q = 0; q < 2; q++)
            boff[q] = (uint32_t)((nb2 + q * 16 + brow) * GPADH + bkh) * 2;
    }

    auto prefetch = [&](int kt){
        int st = kt % ST;
        uint32_t ab = sbase + (uint32_t)(st * 2 * STAGE_H) * 2;
        uint32_t bb = ab + STAGE_H * 2;
        int kc = kt * BK;
        #pragma unroll
        for (int i = 0; i < 4; i++) {
            int id = tid + i * 256, r = id >> 3, c8 = (id & 7) * 8;
            uint32_t off = (uint32_t)(r * GPADH + c8) * 2;
            cp16(ab + off, &A[(size_t)(m0 + r) * K + kc + c8], 16);
            int nr = n0 + r;
            cp16(bb + off, &Bw[(size_t)(nr < N ? nr : 0) * K + kc + c8],
                 nr < N ? 16 : 0);
        }
        asm volatile("cp.async.commit_group;" ::: "memory");
    };

    prefetch(0); prefetch(1); prefetch(2);

    for (int kt = 0; kt < nk; kt++) {
        int allow = nk - 1 - kt; if (allow > ST - 1) allow = ST - 1;
        switch (allow) {
            case 2: asm volatile("cp.async.wait_group 2;" ::: "memory"); break;
            case 1: asm volatile("cp.async.wait_group 1;" ::: "memory"); break;
            default: asm volatile("cp.async.wait_group 0;" ::: "memory"); break;
        }
        __syncthreads();

        int st = kt % ST;
        uint32_t Ast = sbase + (uint32_t)(st * 2 * STAGE_H) * 2;
        uint32_t Bst = Ast + STAGE_H * 2;

        #pragma unroll
        for (int s = 0; s < 4; s++) {
            uint32_t kb = (uint32_t)(s * 16) * 2;
            uint32_t a[4][4], b[4][2];
            #pragma unroll
            for (int mi = 0; mi < 4; mi++)
                LDSM4(a[mi][0], a[mi][1], a[mi][2], a[mi][3], Ast + aoff[mi] + kb);
            #pragma unroll
            for (int q = 0; q < 2; q++)
                LDSM4(b[2*q][0], b[2*q][1], b[2*q+1][0], b[2*q+1][1],
                      Bst + boff[q] + kb);
            #pragma unroll
            for (int mi = 0; mi < 4; mi++)
                #pragma unroll
                for (int ni = 0; ni < 4; ni++) {
                    asm volatile(
                        "mma.sync.aligned.m16n8k16.row.col.f32.f16.f16.f32 "
                        "{%0,%1,%2,%3}, {%4,%5,%6,%7}, {%8,%9}, {%0,%1,%2,%3};"
                        : "+f"(c[mi][ni][0]), "+f"(c[mi][ni][1]),
                          "+f"(c[mi][ni][2]), "+f"(c[mi][ni][3])
                        : "r"(a[mi][0]), "r"(a[mi][1]), "r"(a[mi][2]), "r"(a[mi][3]),
                          "r"(b[ni][0]), "r"(b[ni][1]));
                }
        }
        __syncthreads();
        if (kt + ST < nk) prefetch(kt + ST);
    }

    if (c_half) {
        __half* C = (__half*)C0 + (size_t)blockIdx.z * sC;
        #pragma unroll
        for (int mi = 0; mi < 4; mi++) {
            int row = m0 + mb + mi * 16 + grp;
            #pragma unroll
            for (int ni = 0; ni < 4; ni++) {
                int col = n0 + nb2 + ni * 8 + tig * 2;
                if (col < N) {
                    __half2 h0 = __floats2half2_rn(c[mi][ni][0], c[mi][ni][1]);
                    __half2 h1 = __floats2half2_rn(c[mi][ni][2], c[mi][ni][3]);
                    *(__half2*)&C[(size_t)row * ldc + col]       = h0;
                    *(__half2*)&C[(size_t)(row + 8) * ldc + col] = h1;
                }
            }
        }
    } else {
        float* C = (float*)C0 + (size_t)blockIdx.z * sC;
        #pragma unroll
        for (int mi = 0; mi < 4; mi++) {
            int row = m0 + mb + mi * 16 + grp;
            #pragma unroll
            for (int ni = 0; ni < 4; ni++) {
                int col = n0 + nb2 + ni * 8 + tig * 2;
                if (col < N) {
                    float v0 = c[mi][ni][0], v1 = c[mi][ni][1];
                    float v2 = c[mi][ni][2], v3 = c[mi][ni][3];
                    if (R) {
                        float2 r0 = *(const float2*)&R[(size_t)row * ldc + col];
                        float2 r1 = *(const float2*)&R[(size_t)(row + 8) * ldc + col];
                        v0 += r0.x; v1 += r0.y; v2 += r1.x; v3 += r1.y;
                    }
                    *(float2*)&C[(size_t)row * ldc + col]       = make_float2(v0, v1);
                    *(float2*)&C[(size_t)(row + 8) * ldc + col] = make_float2(v2, v3);
                }
            }
        }
    }
}

// ---------------- K3: conv1d + silu, 8 channels/thread + dt ----------------
__global__ void k_conv3(const float* __restrict__ fw, const float* __restrict__ fb,
                        const float* __restrict__ bw2, const float* __restrict__ bb,
                        const float* __restrict__ fdtb, const float* __restrict__ fA,
                        const float* __restrict__ bdtb, const float* __restrict__ bA)
{
    int token = blockIdx.x, dir = blockIdx.y;
    int b = token >> 10, s = token & 1023;
    const float* w  = dir ? bw2 : fw;
    const float* cb = dir ? bb : fb;
    const __half* zx = g_zx[dir];
    int c = threadIdx.x * 8;

    float acc[8];
    #pragma unroll
    for (int j = 0; j < 8; j++) acc[j] = cb[c + j];
    float wt[8][4];
    #pragma unroll
    for (int j = 0; j < 8; j++) {
        float4 wv = *(const float4*)&w[(c + j) * 4];
        wt[j][0] = wv.x; wt[j][1] = wv.y; wt[j][2] = wv.z; wt[j][3] = wv.w;
    }

    #pragma unroll
    for (int k = 0; k < 4; k++) {
        int sp = dir ? (s + 3 - k) : (s - 3 + k);
        if (sp >= 0 && sp < LL) {
            uint4 u = *(const uint4*)&zx[(size_t)(b * LL + sp) * DIP + DI + c];
            float2 f0 = __half22float2(*(__half2*)&u.x);
            float2 f1 = __half22float2(*(__half2*)&u.y);
            float2 f2 = __half22float2(*(__half2*)&u.z);
            float2 f3 = __half22float2(*(__half2*)&u.w);
            acc[0] = fmaf(f0.x, wt[0][k], acc[0]);
            acc[1] = fmaf(f0.y, wt[1][k], acc[1]);
            acc[2] = fmaf(f1.x, wt[2][k], acc[2]);
            acc[3] = fmaf(f1.y, wt[3][k], acc[3]);
            acc[4] = fmaf(f2.x, wt[4][k], acc[4]);
            acc[5] = fmaf(f2.y, wt[5][k], acc[5]);
            acc[6] = fmaf(f3.x, wt[6][k], acc[6]);
            acc[7] = fmaf(f3.y, wt[7][k], acc[7]);
        }
    }
    __half2 ho[4];
    #pragma unroll
    for (int j = 0; j < 4; j++) {
        float a0 = acc[2*j],   s0 = a0 / (1.f + __expf(-a0));
        float a1 = acc[2*j+1], s1 = a1 / (1.f + __expf(-a1));
        ho[j] = __floats2half2_rn(s0, s1);
    }
    uint4 uo;
    uo.x = *(uint32_t*)&ho[0]; uo.y = *(uint32_t*)&ho[1];
    uo.z = *(uint32_t*)&ho[2]; uo.w = *(uint32_t*)&ho[3];
    *(uint4*)&g_conv[dir][(size_t)token * CD + c] = uo;

    if (threadIdx.x < NH) {
        int h = threadIdx.x;
        float v = __half2float(zx[(size_t)token * DIP + DI + CD + h]) + (dir ? bdtb : fdtb)[h];
        float dt = (v > 20.f) ? v : log1pf(expf(v));
        g_dt[dir][token * NH + h]  = dt;
        g_dec[dir][token * NH + h] = expf(-dt * expf((dir ? bA : fA)[h]));
    }
}

// ---- K4: monolithic selective scan (R10 champion) with TC=16 and
//          load/store spread across all 1024 threads --------------------------
#define TC   16
#define EPW  (TC*200)     // staging elements per epoch (3200)
__global__ void __launch_bounds__(1024, 1) k_scan(const float* __restrict__ fD,
                                                  const float* __restrict__ bD)
{
    int blk = blockIdx.x;
    int dir = blk >> 6, b = (blk >> 4) & 3, h = blk & 15;
    const __half* conv = g_conv[dir];
    const float* dts  = g_dt[dir];
    const float* decs = g_dec[dir];
    float* y = g_y[dir];
    float Dh = (dir ? bD : fD)[h];

    int tid = threadIdx.x;
    int p  = tid >> 4;
    int ns = (tid & 15) * 4;

    uint64_t st2[2] = {0ull, 0ull};

    __shared__ __align__(16) float sm[TC][200];
    float v[4];

    auto load_chunk = [&](int ch){
        #pragma unroll
        for (int pass = 0; pass < 4; pass++) {
            int idx = tid + pass * 1024;
            if (idx < EPW) {
                int tt = idx / 200, item = idx - tt * 200;
                if (item < 194) {
                    int t = ch * TC + tt;
                    int s = dir ? (LL - 1 - t) : t;
                    int token = b * LL + s;
                    if (item < 192) {
                        int c = (item < 64) ? (h * 64 + item)
                              : (item < 128) ? (DI + (item - 64))
                                             : (DI + 64 + (item - 128));
                        v[pass] = __half2float(conv[(size_t)token * CD + c]);
                    } else if (item == 192) v[pass] = decs[token * NH + h];
                    else                    v[pass] = dts[token * NH + h];
                }
            }
        }
    };
    auto store_chunk = [&](){
        #pragma unroll
        for (int pass = 0; pass < 4; pass++) {
            int idx = tid + pass * 1024;
            if (idx < EPW) {
                int tt = idx / 200, item = idx - tt * 200;
                if (item < 194) sm[tt][item] = v[pass];
            }
        }
    };

    load_chunk(0);
    const int NCH = LL / TC;
    for (int ch = 0; ch < NCH; ch++) {
        __syncthreads();
        store_chunk();
        __syncthreads();
        if (ch + 1 < NCH) load_chunk(ch + 1);

        #pragma unroll
        for (int tt = 0; tt < TC; tt++) {
            int t = ch * TC + tt;
            int s = dir ? (LL - 1 - t) : t;
            int token = b * LL + s;
            float dec = sm[tt][192], dtv = sm[tt][193], xv = sm[tt][p];
            uint64_t dec2 = pk2(dec, dec);
            float dtx = dtv * xv;
            uint64_t dtx2 = pk2(dtx, dtx);
            ulonglong2 bq = *(const ulonglong2*)&sm[tt][64 + ns];
            ulonglong2 cq = *(const ulonglong2*)&sm[tt][128 + ns];
            st2[0] = ffma2(st2[0], dec2, mul2(dtx2, bq.x));
            st2[1] = ffma2(st2[1], dec2, mul2(dtx2, bq.y));
            uint64_t acc2 = mul2(st2[0], cq.x);
            acc2 = ffma2(st2[1], cq.y, acc2);
            float acc = __uint_as_float((uint32_t)acc2)
                      + __uint_as_float((uint32_t)(acc2 >> 32));
            acc += __shfl_xor_sync(0xffffffffu, acc, 1);
            acc += __shfl_xor_sync(0xffffffffu, acc, 2);
            acc += __shfl_xor_sync(0xffffffffu, acc, 4);
            acc += __shfl_xor_sync(0xffffffffu, acc, 8);
            if ((tid & 15) == 0)
                y[(size_t)token * DI + h * 64 + p] = acc + Dh * xv;
        }
    }
}

// ---------------- K5: gate (y*silu(z)) + rmsnorm -> fp16 ----------
__global__ void k_gatenorm(const float* __restrict__ f_gw, const float* __restrict__ b_gw)
{
    int row = blockIdx.x, dir = blockIdx.y;
    const float* gw = dir ? b_gw : f_gw;
    const __half* z = g_zx[dir] + (size_t)row * DIP;
    const float* y = g_y[dir] + (size_t)row * DI;
    __half* yo = g_yh[dir] + (size_t)row * DI;
    int tid = threadIdx.x;

    float g[4];
    float ss = 0.f;
    #pragma unroll
    for (int i = 0; i < 4; i++) {
        int cidx = tid + i * 256;
        float zv = __half2float(z[cidx]);
        float gv = y[cidx] * (zv / (1.f + __expf(-zv)));
        g[i] = gv;
        ss += gv * gv;
    }
    __shared__ float red[8];
    float tot = block_reduce_sum_256(ss, red);
    float scale = rsqrtf(tot / (float)DI + 1e-5f);
    #pragma unroll
    for (int i = 0; i < 4; i++) {
        int cidx = tid + i * 256;
        yo[cidx] = __float2half_rn(g[i] * scale * gw[cidx]);
    }
}

// ---------------- launcher ----------------
extern "C" void kernel_launch(void* const* d_in, const int* in_sizes, int n_in,
                              void* d_out, int out_size)
{
    (void)in_sizes; (void)n_in; (void)out_size;
    const float* x       = (const float*)d_in[0];
    const float* norm_w  = (const float*)d_in[1];
    const float* in_w[2]   = {(const float*)d_in[2],  (const float*)d_in[10]};
    const float* conv_w[2] = {(const float*)d_in[3],  (const float*)d_in[11]};
    const float* conv_b[2] = {(const float*)d_in[4],  (const float*)d_in[12]};
    const float* dt_b[2]   = {(const float*)d_in[5],  (const float*)d_in[13]};
    const float* A_log[2]  = {(const float*)d_in[6],  (const float*)d_in[14]};
    const float* Dp[2]     = {(const float*)d_in[7],  (const float*)d_in[15]};
    const float* gnorm[2]  = {(const float*)d_in[8],  (const float*)d_in[16]};
    const float* out_w[2]  = {(const float*)d_in[9],  (const float*)d_in[17]};
    const float* proj_w    = (const float*)d_in[18];
    float* out = (float*)d_out;

    __half *p_h, *p_zx, *p_yh, *p_cat, *p_w;
    cudaGetSymbolAddress((void**)&p_h,   g_h);
    cudaGetSymbolAddress((void**)&p_zx,  g_zx);
    cudaGetSymbolAddress((void**)&p_yh,  g_yh);
    cudaGetSymbolAddress((void**)&p_cat, g_cat);
    cudaGetSymbolAddress((void**)&p_w,   g_wh);

    cudaFuncSetAttribute(k_gemm,
                         cudaFuncAttributeMaxDynamicSharedMemorySize, GEMM_SMEM);

    // 0. fused weight prep + input rmsnorm
    k_prep_norm<<<PREP_BLOCKS + MM, 256>>>(x, norm_w, in_w[0], in_w[1],
                                           out_w[0], out_w[1], proj_w);

    // 1. in_proj both dirs
    {
        dim3 grid((DIP + 127) / 128, MM / 128, 2);
        k_gemm<<<grid, 256, GEMM_SMEM>>>(p_h, 0LL,
                                         p_w + W_IN0, (long long)NW_IN,
                                         p_zx, (long long)MM * DIP,
                                         nullptr, DIP, DM, DIP, 1);
    }

    // 2. conv + silu + dt
    {
        dim3 cgrid(MM, 2);
        k_conv3<<<cgrid, CD / 8>>>(conv_w[0], conv_b[0], conv_w[1], conv_b[1],
                                   dt_b[0], A_log[0], dt_b[1], A_log[1]);
    }

    // 3. monolithic scan (launch 3 -> profiled slot)
    k_scan<<<128, 1024>>>(Dp[0], Dp[1]);

    // 4. gate + rmsnorm
    {
        dim3 grid(MM, 2);
        k_gatenorm<<<grid, 256>>>(gnorm[0], gnorm[1]);
    }

    // 5. out_proj both dirs
    {
        dim3 grid(DM / 128, MM / 128, 2);
        k_gemm<<<grid, 256, GEMM_SMEM>>>(p_yh, (long long)MM * DI,
                                         p_w + W_OUT0, (long long)NW_OUT,
                                         p_cat, (long long)DM,
                                         nullptr, DM, DI, 2 * DM, 1);
    }

    // 6. final: out = x + cat @ proj_w^T
    {
        dim3 grid(DM / 128, MM / 128, 1);
        k_gemm<<<grid, 256, GEMM_SMEM>>>(p_cat, 0LL,
                                         p_w + W_PROJ, 0LL,
                                         out, 0LL,
                                         x, DM, 2 * DM, DM, 0);
    }
}

// round 17
// speedup vs baseline: 1.2996x; 1.0003x over previous
#include <cuda_runtime.h>
#include <cuda_fp16.h>
#include <math.h>
#include <stdint.h>

#define BB   4
#define LL   1024
#define DM   512
#define DI   1024
#define DS   64
#define NH   16
#define CD   1152
#define DIP  2192
#define MM   (BB*LL)

#define NW_IN   (DIP*DM)
#define NW_OUT  (DM*DI)
#define W_IN0   0
#define W_OUT0  (2*NW_IN)
#define W_PROJ  (2*NW_IN + 2*NW_OUT)
#define W_TOT   (W_PROJ + DM*2*DM)

__device__ __align__(128) __half g_h   [MM*DM];
__device__ __align__(128) __half g_zx  [2][MM*DIP];
__device__ __align__(128) __half g_conv[2][MM*CD];
__device__ __align__(128) float  g_dt  [2][MM*NH];
__device__ __align__(128) float  g_dec [2][MM*NH];
__device__ __align__(128) float  g_y   [2][MM*DI];
__device__ __align__(128) __half g_yh  [2][MM*DI];
__device__ __align__(128) __half g_cat [MM*2*DM];
__device__ __align__(128) __half g_wh  [W_TOT];

// ---------------- helpers ----------------
__device__ __forceinline__ uint32_t cvta_s(const void* p){
    uint32_t a;
    asm("{ .reg .u64 t; cvta.to.shared.u64 t, %1; cvt.u32.u64 %0, t; }":"=r"(a):"l"(p));
    return a;
}
__device__ __forceinline__ void cp16(uint32_t dst, const void* src, int sz){
    asm volatile("{ .reg .u64 g; cvta.to.global.u64 g, %1;\n\t"
                 "cp.async.cg.shared.global [%0], [g], 16, %2; }"
                 :: "r"(dst), "l"(src), "r"(sz) : "memory");
}
__device__ __forceinline__ uint64_t pk2(float a, float b){
    uint64_t r; asm("mov.b64 %0, {%1,%2};" : "=l"(r) : "f"(a), "f"(b)); return r;
}
__device__ __forceinline__ uint64_t ffma2(uint64_t a, uint64_t b, uint64_t c){
    uint64_t d; asm("fma.rn.f32x2 %0, %1, %2, %3;" : "=l"(d) : "l"(a), "l"(b), "l"(c)); return d;
}
__device__ __forceinline__ uint64_t mul2(uint64_t a, uint64_t b){
    uint64_t d; asm("mul.rn.f32x2 %0, %1, %2;" : "=l"(d) : "l"(a), "l"(b)); return d;
}

__device__ __forceinline__ float block_reduce_sum_256(float v, float* red) {
    int tid = threadIdx.x;
    #pragma unroll
    for (int o = 16; o; o >>= 1) v += __shfl_xor_sync(0xffffffffu, v, o);
    if ((tid & 31) == 0) red[tid >> 5] = v;
    __syncthreads();
    float t = (tid < 8) ? red[tid] : 0.f;
    if (tid < 32) {
        #pragma unroll
        for (int o = 4; o; o >>= 1) t += __shfl_xor_sync(0xffffffffu, t, o);
        if (tid == 0) red[0] = t;
    }
    __syncthreads();
    return red[0];
}

// ---- K0: fused weight-convert + input rmsnorm ----------
#define PREP_BLOCKS ((W_TOT + 255) / 256)
__global__ void k_prep_norm(const float* __restrict__ x, const float* __restrict__ nw,
                            const float* __restrict__ iw0, const float* __restrict__ iw1,
                            const float* __restrict__ ow0, const float* __restrict__ ow1,
                            const float* __restrict__ pw)
{
    if (blockIdx.x < PREP_BLOCKS) {
        long long i = (long long)blockIdx.x * 256 + threadIdx.x;
        if (i >= W_TOT) return;
        float v;
        if      (i < NW_IN)              v = iw0[i];
        else if (i < 2*NW_IN)            v = iw1[i - NW_IN];
        else if (i < 2*NW_IN + NW_OUT)   v = ow0[i - 2*NW_IN];
        else if (i < W_PROJ)             v = ow1[i - 2*NW_IN - NW_OUT];
        else                             v = pw [i - W_PROJ];
        g_wh[i] = __float2half_rn(v);
    } else {
        int row = blockIdx.x - PREP_BLOCKS, tid = threadIdx.x;
        const float* xr = x + (size_t)row * DM;
        float v0 = xr[tid], v1 = xr[tid + 256];
        __shared__ float red[8];
        float ss = block_reduce_sum_256(v0 * v0 + v1 * v1, red);
        float scale = rsqrtf(ss / (float)DM + 1e-5f);
        g_h[(size_t)row * DM + tid]       = __float2half_rn(v0 * scale * nw[tid]);
        g_h[(size_t)row * DM + tid + 256] = __float2half_rn(v1 * scale * nw[tid + 256]);
    }
}

// ---------------- K2: fp16 mma.sync NT GEMM (R8 mainloop, best measured) ----
#define ST     3
#define BK     64
#define GPADH  72
#define STAGE_H (128*GPADH)
#define GEMM_SMEM (ST*2*STAGE_H*2)           // 110592 bytes

#define LDSM4(r0,r1,r2,r3,addr) \
    asm volatile("ldmatrix.sync.aligned.m8n8.x4.shared.b16 {%0,%1,%2,%3}, [%4];" \
        : "=r"(r0), "=r"(r1), "=r"(r2), "=r"(r3) : "r"(addr))

__global__ void __launch_bounds__(256, 2) k_gemm(
    const __half* __restrict__ A0, long long sA,
    const __half* __restrict__ B0, long long sB,
    void* C0, long long sC,
    const float* __restrict__ R,
    int N, int K, int ldc, int c_half)
{
    extern __shared__ __half smh[];
    const __half* A  = A0 + (size_t)blockIdx.z * sA;
    const __half* Bw = B0 + (size_t)blockIdx.z * sB;

    uint32_t sbase = cvta_s(smh);
    int tid = threadIdx.x, warp = tid >> 5, lane = tid & 31;
    int grp = lane >> 2, tig = lane & 3;
    int m0 = blockIdx.y * 128, n0 = blockIdx.x * 128;
    int mb = (warp & 1) * 64, nb2 = (warp >> 1) * 32;

    float c[4][4][4];
    #pragma unroll
    for (int mi = 0; mi < 4; mi++)
        #pragma unroll
        for (int ni = 0; ni < 4; ni++)
            #pragma unroll
            for (int q = 0; q < 4; q++) c[mi][ni][q] = 0.f;

    const int nk = K / BK;

    uint32_t aoff[4], boff[2];
    {
        int l15 = lane & 15;
        int khalf = (lane >> 4) * 8;
        #pragma unroll
        for (int mi = 0; mi < 4; mi++)
            aoff[mi] = (uint32_t)((mb + mi * 16 + l15) * GPADH + khalf) * 2;
        int brow = (lane & 7) + ((lane >> 4) << 3);
        int bkh  = (lane & 8) ? 8 : 0;
        #pragma unroll
        for (int q = 0; q < 2; q++)
            boff[q] = (uint32_t)((nb2 + q * 16 + brow) * GPADH + bkh) * 2;
    }

    auto prefetch = [&](int kt){
        int st = kt % ST;
        uint32_t ab = sbase + (uint32_t)(st * 2 * STAGE_H) * 2;
        uint32_t bb = ab + STAGE_H * 2;
        int kc = kt * BK;
        #pragma unroll
        for (int i = 0; i < 4; i++) {
            int id = tid + i * 256, r = id >> 3, c8 = (id & 7) * 8;
            uint32_t off = (uint32_t)(r * GPADH + c8) * 2;
            cp16(ab + off, &A[(size_t)(m0 + r) * K + kc + c8], 16);
            int nr = n0 + r;
            cp16(bb + off, &Bw[(size_t)(nr < N ? nr : 0) * K + kc + c8],
                 nr < N ? 16 : 0);
        }
        asm volatile("cp.async.commit_group;" ::: "memory");
    };

    prefetch(0); prefetch(1); prefetch(2);

    for (int kt = 0; kt < nk; kt++) {
        int allow = nk - 1 - kt; if (allow > ST - 1) allow = ST - 1;
        switch (allow) {
            case 2: asm volatile("cp.async.wait_group 2;" ::: "memory"); break;
            case 1: asm volatile("cp.async.wait_group 1;" ::: "memory"); break;
            default: asm volatile("cp.async.wait_group 0;" ::: "memory"); break;
        }
        __syncthreads();

        int st = kt % ST;
        uint32_t Ast = sbase + (uint32_t)(st * 2 * STAGE_H) * 2;
        uint32_t Bst = Ast + STAGE_H * 2;

        #pragma unroll
        for (int s = 0; s < 4; s++) {
            uint32_t kb = (uint32_t)(s * 16) * 2;
            uint32_t a[4][4], b[4][2];
            #pragma unroll
            for (int mi = 0; mi < 4; mi++)
                LDSM4(a[mi][0], a[mi][1], a[mi][2], a[mi][3], Ast + aoff[mi] + kb);
            #pragma unroll
            for (int q = 0; q < 2; q++)
                LDSM4(b[2*q][0], b[2*q][1], b[2*q+1][0], b[2*q+1][1],
                      Bst + boff[q] + kb);
            #pragma unroll
            for (int mi = 0; mi < 4; mi++)
                #pragma unroll
                for (int ni = 0; ni < 4; ni++) {
                    asm volatile(
                        "mma.sync.aligned.m16n8k16.row.col.f32.f16.f16.f32 "
                        "{%0,%1,%2,%3}, {%4,%5,%6,%7}, {%8,%9}, {%0,%1,%2,%3};"
                        : "+f"(c[mi][ni][0]), "+f"(c[mi][ni][1]),
                          "+f"(c[mi][ni][2]), "+f"(c[mi][ni][3])
                        : "r"(a[mi][0]), "r"(a[mi][1]), "r"(a[mi][2]), "r"(a[mi][3]),
                          "r"(b[ni][0]), "r"(b[ni][1]));
                }
        }
        __syncthreads();
        if (kt + ST < nk) prefetch(kt + ST);
    }

    if (c_half) {
        __half* C = (__half*)C0 + (size_t)blockIdx.z * sC;
        #pragma unroll
        for (int mi = 0; mi < 4; mi++) {
            int row = m0 + mb + mi * 16 + grp;
            #pragma unroll
            for (int ni = 0; ni < 4; ni++) {
                int col = n0 + nb2 + ni * 8 + tig * 2;
                if (col < N) {
                    __half2 h0 = __floats2half2_rn(c[mi][ni][0], c[mi][ni][1]);
                    __half2 h1 = __floats2half2_rn(c[mi][ni][2], c[mi][ni][3]);
                    *(__half2*)&C[(size_t)row * ldc + col]       = h0;
                    *(__half2*)&C[(size_t)(row + 8) * ldc + col] = h1;
                }
            }
        }
    } else {
        float* C = (float*)C0 + (size_t)blockIdx.z * sC;
        #pragma unroll
        for (int mi = 0; mi < 4; mi++) {
            int row = m0 + mb + mi * 16 + grp;
            #pragma unroll
            for (int ni = 0; ni < 4; ni++) {
                int col = n0 + nb2 + ni * 8 + tig * 2;
                if (col < N) {
                    float v0 = c[mi][ni][0], v1 = c[mi][ni][1];
                    float v2 = c[mi][ni][2], v3 = c[mi][ni][3];
                    if (R) {
                        float2 r0 = *(const float2*)&R[(size_t)row * ldc + col];
                        float2 r1 = *(const float2*)&R[(size_t)(row + 8) * ldc + col];
                        v0 += r0.x; v1 += r0.y; v2 += r1.x; v3 += r1.y;
                    }
                    *(float2*)&C[(size_t)row * ldc + col]       = make_float2(v0, v1);
                    *(float2*)&C[(size_t)(row + 8) * ldc + col] = make_float2(v2, v3);
                }
            }
        }
    }
}

// ---------------- K3: conv1d + silu, 8 channels/thread + dt ----------------
__global__ void k_conv3(const float* __restrict__ fw, const float* __restrict__ fb,
                        const float* __restrict__ bw2, const float* __restrict__ bb,
                        const float* __restrict__ fdtb, const float* __restrict__ fA,
                        const float* __restrict__ bdtb, const float* __restrict__ bA)
{
    int token = blockIdx.x, dir = blockIdx.y;
    int b = token >> 10, s = token & 1023;
    const float* w  = dir ? bw2 : fw;
    const float* cb = dir ? bb : fb;
    const __half* zx = g_zx[dir];
    int c = threadIdx.x * 8;

    float acc[8];
    #pragma unroll
    for (int j = 0; j < 8; j++) acc[j] = cb[c + j];
    float wt[8][4];
    #pragma unroll
    for (int j = 0; j < 8; j++) {
        float4 wv = *(const float4*)&w[(c + j) * 4];
        wt[j][0] = wv.x; wt[j][1] = wv.y; wt[j][2] = wv.z; wt[j][3] = wv.w;
    }

    #pragma unroll
    for (int k = 0; k < 4; k++) {
        int sp = dir ? (s + 3 - k) : (s - 3 + k);
        if (sp >= 0 && sp < LL) {
            uint4 u = *(const uint4*)&zx[(size_t)(b * LL + sp) * DIP + DI + c];
            float2 f0 = __half22float2(*(__half2*)&u.x);
            float2 f1 = __half22float2(*(__half2*)&u.y);
            float2 f2 = __half22float2(*(__half2*)&u.z);
            float2 f3 = __half22float2(*(__half2*)&u.w);
            acc[0] = fmaf(f0.x, wt[0][k], acc[0]);
            acc[1] = fmaf(f0.y, wt[1][k], acc[1]);
            acc[2] = fmaf(f1.x, wt[2][k], acc[2]);
            acc[3] = fmaf(f1.y, wt[3][k], acc[3]);
            acc[4] = fmaf(f2.x, wt[4][k], acc[4]);
            acc[5] = fmaf(f2.y, wt[5][k], acc[5]);
            acc[6] = fmaf(f3.x, wt[6][k], acc[6]);
            acc[7] = fmaf(f3.y, wt[7][k], acc[7]);
        }
    }
    __half2 ho[4];
    #pragma unroll
    for (int j = 0; j < 4; j++) {
        float a0 = acc[2*j],   s0 = a0 / (1.f + __expf(-a0));
        float a1 = acc[2*j+1], s1 = a1 / (1.f + __expf(-a1));
        ho[j] = __floats2half2_rn(s0, s1);
    }
    uint4 uo;
    uo.x = *(uint32_t*)&ho[0]; uo.y = *(uint32_t*)&ho[1];
    uo.z = *(uint32_t*)&ho[2]; uo.w = *(uint32_t*)&ho[3];
    *(uint4*)&g_conv[dir][(size_t)token * CD + c] = uo;

    if (threadIdx.x < NH) {
        int h = threadIdx.x;
        float v = __half2float(zx[(size_t)token * DIP + DI + CD + h]) + (dir ? bdtb : fdtb)[h];
        float dt = (v > 20.f) ? v : log1pf(expf(v));
        g_dt[dir][token * NH + h]  = dt;
        g_dec[dir][token * NH + h] = expf(-dt * expf((dir ? bA : fA)[h]));
    }
}

// ---- K4: monolithic scan, TC=16, double-buffered staging, ONE barrier/epoch --
#define TC   16
#define EPW  (TC*200)     // staging elements per epoch (3200)
__global__ void __launch_bounds__(1024, 1) k_scan(const float* __restrict__ fD,
                                                  const float* __restrict__ bD)
{
    int blk = blockIdx.x;
    int dir = blk >> 6, b = (blk >> 4) & 3, h = blk & 15;
    const __half* conv = g_conv[dir];
    const float* dts  = g_dt[dir];
    const float* decs = g_dec[dir];
    float* y = g_y[dir];
    float Dh = (dir ? bD : fD)[h];

    int tid = threadIdx.x;
    int p  = tid >> 4;
    int ns = (tid & 15) * 4;

    uint64_t st2[2] = {0ull, 0ull};

    __shared__ __align__(16) float sm[2][TC][200];
    float v[4];

    auto load_chunk = [&](int ch){
        #pragma unroll
        for (int pass = 0; pass < 4; pass++) {
            int idx = tid + pass * 1024;
            if (idx < EPW) {
                int tt = idx / 200, item = idx - tt * 200;
                if (item < 194) {
                    int t = ch * TC + tt;
                    int s = dir ? (LL - 1 - t) : t;
                    int token = b * LL + s;
                    if (item < 192) {
                        int c = (item < 64) ? (h * 64 + item)
                              : (item < 128) ? (DI + (item - 64))
                                             : (DI + 64 + (item - 128));
                        v[pass] = __half2float(conv[(size_t)token * CD + c]);
                    } else if (item == 192) v[pass] = decs[token * NH + h];
                    else                    v[pass] = dts[token * NH + h];
                }
            }
        }
    };
    auto store_chunk = [&](int buf){
        #pragma unroll
        for (int pass = 0; pass < 4; pass++) {
            int idx = tid + pass * 1024;
            if (idx < EPW) {
                int tt = idx / 200, item = idx - tt * 200;
                if (item < 194) sm[buf][tt][item] = v[pass];
            }
        }
    };

    load_chunk(0);
    store_chunk(0);
    __syncthreads();

    const int NCH = LL / TC;
    for (int ch = 0; ch < NCH; ch++) {
        int cur = ch & 1;
        if (ch + 1 < NCH) load_chunk(ch + 1);   // LDGs overlap compute below

        #pragma unroll
        for (int tt = 0; tt < TC; tt++) {
            int t = ch * TC + tt;
            int s = dir ? (LL - 1 - t) : t;
            int token = b * LL + s;
            float dec = sm[cur][tt][192], dtv = sm[cur][tt][193], xv = sm[cur][tt][p];
            uint64_t dec2 = pk2(dec, dec);
            float dtx = dtv * xv;
            uint64_t dtx2 = pk2(dtx, dtx);
            ulonglong2 bq = *(const ulonglong2*)&sm[cur][tt][64 + ns];
            ulonglong2 cq = *(const ulonglong2*)&sm[cur][tt][128 + ns];
            st2[0] = ffma2(st2[0], dec2, mul2(dtx2, bq.x));
            st2[1] = ffma2(st2[1], dec2, mul2(dtx2, bq.y));
            uint64_t acc2 = mul2(st2[0], cq.x);
            acc2 = ffma2(st2[1], cq.y, acc2);
            float acc = __uint_as_float((uint32_t)acc2)
                      + __uint_as_float((uint32_t)(acc2 >> 32));
            acc += __shfl_xor_sync(0xffffffffu, acc, 1);
            acc += __shfl_xor_sync(0xffffffffu, acc, 2);
            acc += __shfl_xor_sync(0xffffffffu, acc, 4);
            acc += __shfl_xor_sync(0xffffffffu, acc, 8);
            if ((tid & 15) == 0)
                y[(size_t)token * DI + h * 64 + p] = acc + Dh * xv;
        }

        if (ch + 1 < NCH) store_chunk(cur ^ 1);  // loads complete by now
        __syncthreads();                          // publish buf[cur^1]
    }
}

// ---------------- K5: gate (y*silu(z)) + rmsnorm -> fp16 ----------
__global__ void k_gatenorm(const float* __restrict__ f_gw, const float* __restrict__ b_gw)
{
    int row = blockIdx.x, dir = blockIdx.y;
    const float* gw = dir ? b_gw : f_gw;
    const __half* z = g_zx[dir] + (size_t)row * DIP;
    const float* y = g_y[dir] + (size_t)row * DI;
    __half* yo = g_yh[dir] + (size_t)row * DI;
    int tid = threadIdx.x;

    float g[4];
    float ss = 0.f;
    #pragma unroll
    for (int i = 0; i < 4; i++) {
        int cidx = tid + i * 256;
        float zv = __half2float(z[cidx]);
        float gv = y[cidx] * (zv / (1.f + __expf(-zv)));
        g[i] = gv;
        ss += gv * gv;
    }
    __shared__ float red[8];
    float tot = block_reduce_sum_256(ss, red);
    float scale = rsqrtf(tot / (float)DI + 1e-5f);
    #pragma unroll
    for (int i = 0; i < 4; i++) {
        int cidx = tid + i * 256;
        yo[cidx] = __float2half_rn(g[i] * scale * gw[cidx]);
    }
}

// ---------------- launcher ----------------
extern "C" void kernel_launch(void* const* d_in, const int* in_sizes, int n_in,
                              void* d_out, int out_size)
{
    (void)in_sizes; (void)n_in; (void)out_size;
    const float* x       = (const float*)d_in[0];
    const float* norm_w  = (const float*)d_in[1];
    const float* in_w[2]   = {(const float*)d_in[2],  (const float*)d_in[10]};
    const float* conv_w[2] = {(const float*)d_in[3],  (const float*)d_in[11]};
    const float* conv_b[2] = {(const float*)d_in[4],  (const float*)d_in[12]};
    const float* dt_b[2]   = {(const float*)d_in[5],  (const float*)d_in[13]};
    const float* A_log[2]  = {(const float*)d_in[6],  (const float*)d_in[14]};
    const float* Dp[2]     = {(const float*)d_in[7],  (const float*)d_in[15]};
    const float* gnorm[2]  = {(const float*)d_in[8],  (const float*)d_in[16]};
    const float* out_w[2]  = {(const float*)d_in[9],  (const float*)d_in[17]};
    const float* proj_w    = (const float*)d_in[18];
    float* out = (float*)d_out;

    __half *p_h, *p_zx, *p_yh, *p_cat, *p_w;
    cudaGetSymbolAddress((void**)&p_h,   g_h);
    cudaGetSymbolAddress((void**)&p_zx,  g_zx);
    cudaGetSymbolAddress((void**)&p_yh,  g_yh);
    cudaGetSymbolAddress((void**)&p_cat, g_cat);
    cudaGetSymbolAddress((void**)&p_w,   g_wh);

    cudaFuncSetAttribute(k_gemm,
                         cudaFuncAttributeMaxDynamicSharedMemorySize, GEMM_SMEM);

    // 0. fused weight prep + input rmsnorm
    k_prep_norm<<<PREP_BLOCKS + MM, 256>>>(x, norm_w, in_w[0], in_w[1],
                                           out_w[0], out_w[1], proj_w);

    // 1. in_proj both dirs
    {
        dim3 grid((DIP + 127) / 128, MM / 128, 2);
        k_gemm<<<grid, 256, GEMM_SMEM>>>(p_h, 0LL,
                                         p_w + W_IN0, (long long)NW_IN,
                                         p_zx, (long long)MM * DIP,
                                         nullptr, DIP, DM, DIP, 1);
    }

    // 2. conv + silu + dt
    {
        dim3 cgrid(MM, 2);
        k_conv3<<<cgrid, CD / 8>>>(conv_w[0], conv_b[0], conv_w[1], conv_b[1],
                                   dt_b[0], A_log[0], dt_b[1], A_log[1]);
    }

    // 3. monolithic scan (launch 3 -> profiled slot)
    k_scan<<<128, 1024>>>(Dp[0], Dp[1]);

    // 4. gate + rmsnorm
    {
        dim3 grid(MM, 2);
        k_gatenorm<<<grid, 256>>>(gnorm[0], gnorm[1]);
    }

    // 5. out_proj both dirs
    {
        dim3 grid(DM / 128, MM / 128, 2);
        k_gemm<<<grid, 256, GEMM_SMEM>>>(p_yh, (long long)MM * DI,
                                         p_w + W_OUT0, (long long)NW_OUT,
                                         p_cat, (long long)DM,
                                         nullptr, DM, DI, 2 * DM, 1);
    }

    // 6. final: out = x + cat @ proj_w^T
    {
        dim3 grid(DM / 128, MM / 128, 1);
        k_gemm<<<grid, 256, GEMM_SMEM>>>(p_cat, 0LL,
                                         p_w + W_PROJ, 0LL,
                                         out, 0LL,
                                         x, DM, 2 * DM, DM, 0);
    }
}